// round 13
// baseline (speedup 1.0000x reference)
#include <cuda_runtime.h>
#include <cuda_bf16.h>
#include <stdint.h>

#define Bsz 2048
#define Lx  128
#define Tst 16
#define C1  256
#define C2  128
#define C3  64

// spike bit-planes, layout [..][l][ci-words]
__device__ uint32_t g_s1[(size_t)Tst * Bsz * Lx * (C1 / 32)];  // 134 MB
__device__ uint32_t g_s2[(size_t)Bsz * Lx * (C2 / 32)];
__device__ uint32_t g_s3[(size_t)Bsz * Lx * (C3 / 32)];
__device__ float    g_mem2[(size_t)Bsz * Lx * C2];   // [b][l][co]
__device__ float    g_mem3[(size_t)Bsz * Lx * C3];
__device__ float    g_mem4[(size_t)Bsz * 256];
__device__ float    g_mem5[(size_t)Bsz * 100];

// B fragment tables, lane-contiguous layout:
// u32 idx = (((bi*KT + kt)*2 + wc)*32 + lane)*(NTW*2) + ntl*2 + r
__device__ __align__(16) uint32_t g_fragB2[9 * 16 * 2 * 32 * 16];  // 590 KB
__device__ __align__(16) uint32_t g_fragB3[9 * 8 * 2 * 32 * 8];    // 147 KB

// ---------------------------------------------------------------------------
// 3-way bf16 split: w = hi + mid + lo, residual ~2^-24 relative
// ---------------------------------------------------------------------------
__device__ __forceinline__ uint16_t pick_split(float w, int split) {
    __nv_bfloat16 h = __float2bfloat16(w);
    float r1 = w - __bfloat162float(h);
    __nv_bfloat16 m = __float2bfloat16(r1);
    float r2 = r1 - __bfloat162float(m);
    __nv_bfloat16 lo = __float2bfloat16(r2);
    __nv_bfloat16 v = (split == 0) ? h : (split == 1) ? m : lo;
    return __bfloat16_as_ushort(v);
}

// prep: bake B fragments (mma.m16n8k16 B layout, lane-contiguous uint4 order)
__global__ void prep_kernel(const float* __restrict__ W2,
                            const float* __restrict__ W3) {
    int i = blockIdx.x * blockDim.x + threadIdx.x;
    if (i < 9 * 16 * 2 * 32 * 16) {   // conv2: KT=16, NTW=8
        int j = i;
        int r = j & 1; j >>= 1;
        int ntl = j & 7; j >>= 3;
        int lane = j & 31; j >>= 5;
        int wc = j & 1; j >>= 1;
        int kt = j & 15; j >>= 4;
        int bi = j;                    // k*3 + split
        int k = bi / 3, split = bi % 3;
        int g = lane >> 2, tg = lane & 3;
        int co = (wc * 8 + ntl) * 8 + g;
        int ci0 = kt * 16 + tg * 2 + r * 8;
        uint16_t lo = pick_split(W2[(co * C1 + ci0) * 3 + k], split);
        uint16_t hi = pick_split(W2[(co * C1 + ci0 + 1) * 3 + k], split);
        g_fragB2[i] = (uint32_t)lo | ((uint32_t)hi << 16);
    }
    if (i < 9 * 8 * 2 * 32 * 8) {     // conv3: KT=8, NTW=4
        int j = i;
        int r = j & 1; j >>= 1;
        int ntl = j & 3; j >>= 2;
        int lane = j & 31; j >>= 5;
        int wc = j & 1; j >>= 1;
        int kt = j & 7; j >>= 3;
        int bi = j;
        int k = bi / 3, split = bi % 3;
        int g = lane >> 2, tg = lane & 3;
        int co = (wc * 4 + ntl) * 8 + g;
        int ci0 = kt * 16 + tg * 2 + r * 8;
        uint16_t lo = pick_split(W3[(co * C2 + ci0) * 3 + k], split);
        uint16_t hi = pick_split(W3[(co * C2 + ci0 + 1) * 3 + k], split);
        g_fragB3[i] = (uint32_t)lo | ((uint32_t)hi << 16);
    }
}

// ---------------------------------------------------------------------------
// k0: conv1 + full 16-step layer-1 LIF (time-invariant drive).
// ---------------------------------------------------------------------------
__global__ void k0_kernel(const float* __restrict__ x,
                          const float* __restrict__ W1,
                          const float* __restrict__ b1) {
    int gw   = blockIdx.x * (blockDim.x >> 5) + (threadIdx.x >> 5);
    int lane = threadIdx.x & 31;
    int cw = gw & 7;
    int l  = (gw >> 3) & 127;
    int b  = gw >> 10;
    int co = cw * 32 + lane;

    float cur = b1[co];
#pragma unroll
    for (int ci = 0; ci < 2; ci++) {
        const float* xr = x + ((size_t)b * 2 + ci) * Lx;
        const float* wr = W1 + (co * 2 + ci) * 5;
#pragma unroll
        for (int k = 0; k < 5; k++) {
            int ll = l + k - 2;
            float xv = (ll >= 0 && ll < Lx) ? xr[ll] : 0.0f;
            cur = fmaf(xv, wr[k], cur);
        }
    }
    float m = 0.0f;
#pragma unroll
    for (int t = 0; t < Tst; t++) {
        float r = (m > 1.0f) ? 1.0f : 0.0f;
        m = fmaf(0.9f, m, cur) - r;
        unsigned bal = __ballot_sync(0xffffffffu, m > 1.0f);
        if (lane == 0)
            g_s1[(((size_t)t * Bsz + b) * Lx + l) * 8 + cw] = bal;
    }
}

__device__ __forceinline__ uint32_t bits2bf(uint32_t two) {
    return ((two & 1u) ? 0x3F80u : 0u) | ((two & 2u) ? 0x3F800000u : 0u);
}

// ---------------------------------------------------------------------------
// hmmaconv<CI,CO>: conv-as-GEMM over binary spikes, bf16 HMMA, 3-split W,
// fused LIF + bit-pack. A expanded to bf16 smem ONCE, fragments via ldmatrix.
// CTA = 1 sample, 8 warps = 4(M) x 2(N); warp tile 32 x CO/2.
// dynamic smem: sA = 130 x (CI+8) bf16 rows (halo rows 0,129 zero),
//               sspk = 128*CO spike bytes.
// ---------------------------------------------------------------------------
template <int CI, int CO>
__global__ void __launch_bounds__(256, 2)
hmmaconv_kernel(int t, const uint32_t* __restrict__ sin,
                uint32_t* __restrict__ sout,
                const uint32_t* __restrict__ frag,
                const float* __restrict__ bias,
                float* __restrict__ mem) {
    constexpr int NW  = CI / 32;       // bit-words per row
    constexpr int KT  = CI / 16;       // k16-tiles per shift
    constexpr int NTW = CO / 16;       // n8-tiles per warp
    constexpr int SHW = CI + 8;        // smem row stride (halfwords)

    extern __shared__ __align__(16) char smem[];
    uint16_t* sA   = (uint16_t*)smem;
    uint32_t* sA32 = (uint32_t*)smem;
    uint32_t* sspk = (uint32_t*)(smem + 130 * SHW * 2);

    int tid = threadIdx.x;
    int b   = blockIdx.x;
    int wid = tid >> 5;
    int lane = tid & 31;
    int g = lane >> 2, tg = lane & 3;
    int wm = (wid >> 1) * 32;          // warp M base
    int wc = wid & 1;                  // warp N col

    // expand bit-planes -> bf16 rows 1..128, zero halo rows 0 and 129
    const uint32_t* srow = sin + (size_t)b * Lx * NW;
    for (int j = tid; j < 130 * (CI / 2); j += 256) {
        int r = j / (CI / 2);
        int c = j % (CI / 2);
        uint32_t v = 0u;
        if (r >= 1 && r <= 128) {
            uint32_t w = srow[(r - 1) * NW + (c >> 4)];
            v = bits2bf((w >> ((2 * c) & 31)) & 3u);
        }
        sA32[r * (SHW / 2) + c] = v;
    }
    __syncthreads();

    // ldmatrix per-lane base: row = lane&15, col8 = lane>>4
    uint32_t aBase;
    {
        uint32_t a;
        asm("{ .reg .u64 t; cvta.to.shared.u64 t, %1; cvt.u32.u64 %0, t; }"
            : "=r"(a) : "l"((const void*)sA));
        aBase = a + (((lane & 15) * SHW + (lane >> 4) * 8) * 2);
    }

    float d[2][NTW][4];
#pragma unroll
    for (int mt = 0; mt < 2; mt++)
#pragma unroll
        for (int n = 0; n < NTW; n++)
#pragma unroll
            for (int e = 0; e < 4; e++) d[mt][n][e] = 0.0f;

    const uint4* fragL = (const uint4*)frag +
                         (size_t)wc * 32 * (NTW / 2) + lane * (NTW / 2);

#pragma unroll
    for (int k = 0; k < 3; k++) {
#pragma unroll 1
        for (int kt = 0; kt < KT; kt++) {
            uint32_t a[2][4];
#pragma unroll
            for (int mt = 0; mt < 2; mt++) {
                uint32_t addr = aBase + ((wm + mt * 16 + k) * SHW + kt * 16) * 2;
                asm volatile(
                    "ldmatrix.sync.aligned.m8n8.x4.shared.b16 {%0,%1,%2,%3}, [%4];"
                    : "=r"(a[mt][0]), "=r"(a[mt][1]),
                      "=r"(a[mt][2]), "=r"(a[mt][3])
                    : "r"(addr));
            }
#pragma unroll
            for (int split = 0; split < 3; split++) {
                int bi = k * 3 + split;
                const uint4* fp = fragL + (size_t)(bi * KT + kt) * 32 * NTW;
#pragma unroll
                for (int u = 0; u < NTW / 2; u++) {
                    uint4 q = fp[u];
#pragma unroll
                    for (int mt = 0; mt < 2; mt++) {
                        asm volatile(
                            "mma.sync.aligned.m16n8k16.row.col.f32.bf16.bf16.f32 "
                            "{%0,%1,%2,%3}, {%4,%5,%6,%7}, {%8,%9}, {%0,%1,%2,%3};"
                            : "+f"(d[mt][2 * u][0]), "+f"(d[mt][2 * u][1]),
                              "+f"(d[mt][2 * u][2]), "+f"(d[mt][2 * u][3])
                            : "r"(a[mt][0]), "r"(a[mt][1]),
                              "r"(a[mt][2]), "r"(a[mt][3]),
                              "r"(q.x), "r"(q.y));
                        asm volatile(
                            "mma.sync.aligned.m16n8k16.row.col.f32.bf16.bf16.f32 "
                            "{%0,%1,%2,%3}, {%4,%5,%6,%7}, {%8,%9}, {%0,%1,%2,%3};"
                            : "+f"(d[mt][2 * u + 1][0]), "+f"(d[mt][2 * u + 1][1]),
                              "+f"(d[mt][2 * u + 1][2]), "+f"(d[mt][2 * u + 1][3])
                            : "r"(a[mt][0]), "r"(a[mt][1]),
                              "r"(a[mt][2]), "r"(a[mt][3]),
                              "r"(q.z), "r"(q.w));
                    }
                }
            }
        }
    }
    __syncthreads();   // sA done; sspk region reuse is distinct, but keep order

    // fused LIF epilogue: owner lane updates mem, drops spike byte to smem
    uint8_t* spk8 = (uint8_t*)sspk;
    float* mb = mem + (size_t)b * Lx * CO;
#pragma unroll
    for (int mt = 0; mt < 2; mt++)
#pragma unroll
        for (int n = 0; n < NTW; n++)
#pragma unroll
            for (int e = 0; e < 4; e++) {
                int row = wm + mt * 16 + g + (e >> 1) * 8;
                int co = wc * (CO / 2) + n * 8 + tg * 2 + (e & 1);
                float cur = d[mt][n][e] + __ldg(&bias[co]);
                float m0 = (t == 0) ? 0.0f : mb[row * CO + co];
                float r = (m0 > 1.0f) ? 1.0f : 0.0f;
                float m = fmaf(0.9f, m0, cur) - r;
                mb[row * CO + co] = m;
                spk8[row * CO + co] = (m > 1.0f) ? 1 : 0;
            }
    __syncthreads();

    // pack spike bytes -> bit words [b][l][CO/32]
    constexpr int NWORDS = 128 * (CO / 32);
    uint32_t* so = sout + (size_t)b * Lx * (CO / 32);
    for (int w = tid; w < NWORDS; w += 256) {
        int row = w / (CO / 32);
        int wd = w % (CO / 32);
        const uint32_t* p = &sspk[(row * CO + wd * 32) / 4];
        uint32_t bits = 0;
#pragma unroll
        for (int jj = 0; jj < 8; jj++) {
            uint32_t v = p[jj];
            bits |= ((v >> 0) & 1u) << (jj * 4 + 0);
            bits |= ((v >> 8) & 1u) << (jj * 4 + 1);
            bits |= ((v >> 16) & 1u) << (jj * 4 + 2);
            bits |= ((v >> 24) & 1u) << (jj * 4 + 3);
        }
        so[w] = bits;
    }
}

// ---------------------------------------------------------------------------
// k45: conv4(64->2,K3)+LIF4 + fc1+LIF5 + fc2 accumulate. 256 threads, ILP'd.
// s3 layout [b][l][2 words].
// ---------------------------------------------------------------------------
__global__ void __launch_bounds__(256)
k45_kernel(int t,
           const float* __restrict__ W4, const float* __restrict__ b4,
           const float* __restrict__ fw1, const float* __restrict__ fb1,
           const float* __restrict__ fw2, const float* __restrict__ fb2,
           float* __restrict__ out) {
    __shared__ uint32_t s3w[Lx * 2];
    __shared__ float    w4s[2 * C3 * 3];
    __shared__ float    s4f[256];
    __shared__ float    s5f[100];

    int tid = threadIdx.x;
    int b   = blockIdx.x;

    if (tid < Lx * 2) s3w[tid] = g_s3[(size_t)b * Lx * 2 + tid];
    if (tid < 2 * C3 * 3) w4s[tid] = W4[tid];
    __syncthreads();

    // conv4 + LIF4 : one flat output per thread (o = co*128 + l)
    {
        int o  = tid;
        int co = o >> 7;
        int l  = o & 127;
        float c0 = 0.f, c1 = 0.f, c2 = 0.f, c3 = 0.f;
#pragma unroll
        for (int dk = 0; dk < 3; dk++) {
            int ll = l + dk - 1;
            if (ll >= 0 && ll < Lx) {
                uint32_t w0 = s3w[ll * 2], w1 = s3w[ll * 2 + 1];
                const float* wr = &w4s[co * 192 + dk];
#pragma unroll
                for (int ci = 0; ci < 32; ci += 4) {
                    c0 += ((w0 >> ci) & 1u)       ? wr[ci * 3]       : 0.f;
                    c1 += ((w0 >> (ci + 1)) & 1u) ? wr[(ci + 1) * 3] : 0.f;
                    c2 += ((w0 >> (ci + 2)) & 1u) ? wr[(ci + 2) * 3] : 0.f;
                    c3 += ((w0 >> (ci + 3)) & 1u) ? wr[(ci + 3) * 3] : 0.f;
                }
#pragma unroll
                for (int ci = 0; ci < 32; ci += 4) {
                    c0 += ((w1 >> ci) & 1u)       ? wr[(32 + ci) * 3]  : 0.f;
                    c1 += ((w1 >> (ci + 1)) & 1u) ? wr[(33 + ci) * 3]  : 0.f;
                    c2 += ((w1 >> (ci + 2)) & 1u) ? wr[(34 + ci) * 3]  : 0.f;
                    c3 += ((w1 >> (ci + 3)) & 1u) ? wr[(35 + ci) * 3]  : 0.f;
                }
            }
        }
        float cur = b4[co] + (c0 + c1) + (c2 + c3);
        float m = (t == 0) ? 0.0f : g_mem4[(size_t)b * 256 + o];
        float r = (m > 1.0f) ? 1.0f : 0.0f;
        m = fmaf(0.9f, m, cur) - r;
        g_mem4[(size_t)b * 256 + o] = m;
        s4f[o] = (m > 1.0f) ? 1.0f : 0.0f;
    }
    __syncthreads();

    if (tid < 100) {
        float a0 = 0.f, a1 = 0.f, a2 = 0.f, a3 = 0.f;
        const float* wr = fw1 + (size_t)tid * 256;
#pragma unroll
        for (int j = 0; j < 256; j += 4) {
            a0 = fmaf(s4f[j],     wr[j],     a0);
            a1 = fmaf(s4f[j + 1], wr[j + 1], a1);
            a2 = fmaf(s4f[j + 2], wr[j + 2], a2);
            a3 = fmaf(s4f[j + 3], wr[j + 3], a3);
        }
        float cur = fb1[tid] + (a0 + a1) + (a2 + a3);
        float m = (t == 0) ? 0.0f : g_mem5[(size_t)b * 100 + tid];
        float r = (m > 1.0f) ? 1.0f : 0.0f;
        m = fmaf(0.9f, m, cur) - r;
        g_mem5[(size_t)b * 100 + tid] = m;
        s5f[tid] = (m > 1.0f) ? 1.0f : 0.0f;
    }
    __syncthreads();

    if (tid < 40) {
        float a0 = 0.f, a1 = 0.f;
        const float* wr = fw2 + (size_t)tid * 100;
#pragma unroll
        for (int j = 0; j < 100; j += 2) {
            a0 = fmaf(s5f[j],     wr[j],     a0);
            a1 = fmaf(s5f[j + 1], wr[j + 1], a1);
        }
        float v = a0 + a1;
        size_t oi = (size_t)b * 40 + tid;
        float sum = (t == 0) ? v : (out[oi] + v);
        out[oi] = (t == Tst - 1) ? (sum * (1.0f / Tst) + fb2[tid]) : sum;
    }
}

// ---------------------------------------------------------------------------
extern "C" void kernel_launch(void* const* d_in, const int* in_sizes, int n_in,
                              void* d_out, int out_size) {
    const float* x   = (const float*)d_in[0];
    const float* W1  = (const float*)d_in[1];
    const float* b1  = (const float*)d_in[2];
    const float* W2  = (const float*)d_in[3];
    const float* b2  = (const float*)d_in[4];
    const float* W3  = (const float*)d_in[5];
    const float* b3  = (const float*)d_in[6];
    const float* W4  = (const float*)d_in[7];
    const float* b4  = (const float*)d_in[8];
    const float* fw1 = (const float*)d_in[9];
    const float* fb1 = (const float*)d_in[10];
    const float* fw2 = (const float*)d_in[11];
    const float* fb2 = (const float*)d_in[12];
    float* out = (float*)d_out;

    void *ps1, *ps2, *ps3, *pm2, *pm3, *pf2, *pf3;
    cudaGetSymbolAddress(&ps1, g_s1);
    cudaGetSymbolAddress(&ps2, g_s2);
    cudaGetSymbolAddress(&ps3, g_s3);
    cudaGetSymbolAddress(&pm2, g_mem2);
    cudaGetSymbolAddress(&pm3, g_mem3);
    cudaGetSymbolAddress(&pf2, g_fragB2);
    cudaGetSymbolAddress(&pf3, g_fragB3);

    // dynamic smem sizes: sA (130 rows x (CI+8) bf16) + sspk (128*CO bytes)
    constexpr int SM2 = 130 * (C1 + 8) * 2 + 128 * C2;  // 85024
    constexpr int SM3 = 130 * (C2 + 8) * 2 + 128 * C3;  // 43552
    cudaFuncSetAttribute(hmmaconv_kernel<C1, C2>,
                         cudaFuncAttributeMaxDynamicSharedMemorySize, SM2);
    cudaFuncSetAttribute(hmmaconv_kernel<C2, C3>,
                         cudaFuncAttributeMaxDynamicSharedMemorySize, SM3);

    prep_kernel<<<(9 * 16 * 2 * 32 * 16 + 255) / 256, 256>>>(W2, W3);
    k0_kernel<<<Bsz * Lx, 256>>>(x, W1, b1);

    for (int t = 0; t < Tst; t++) {
        hmmaconv_kernel<C1, C2><<<Bsz, 256, SM2>>>(
            t, (const uint32_t*)ps1 + (size_t)t * Bsz * Lx * 8,
            (uint32_t*)ps2, (const uint32_t*)pf2, b2, (float*)pm2);
        hmmaconv_kernel<C2, C3><<<Bsz, 256, SM3>>>(
            t, (const uint32_t*)ps2,
            (uint32_t*)ps3, (const uint32_t*)pf3, b3, (float*)pm3);
        k45_kernel<<<Bsz, 256>>>(t, W4, b4, fw1, fb1, fw2, fb2, out);
    }
}